// round 3
// baseline (speedup 1.0000x reference)
#include <cuda_runtime.h>
#include <math.h>

#define BB 32
#define EE 512
#define HH 1024
#define G4 4096
#define LL 64
#define VV 32000

typedef unsigned long long u64;

// ---------------- device scratch (no allocations allowed) ----------------
__device__ float g_h[BB*HH];
__device__ float g_c[BB*HH];
__device__ float g_enc[LL*BB*HH];      // [l][b][d]
__device__ float g_e[BB*HH];           // decoder embedding
__device__ float g_ctx[BB*HH];
__device__ float g_inp[BB*HH];
__device__ float g_part[4*BB*G4];      // split-K partials for LSTM gates
__device__ float g_part2[4*BB*HH];     // split-K partials for comb
__device__ int   g_tok[BB];

// ---------------- f32x2 packed helpers (FFMA2 path) ----------------
__device__ __forceinline__ u64 pk(float x, float y){
    u64 r; asm("mov.b64 %0,{%1,%2};" : "=l"(r) : "f"(x), "f"(y)); return r;
}
__device__ __forceinline__ void fma2(u64 &d, u64 a, u64 b){
    asm("fma.rn.f32x2 %0, %1, %2, %0;" : "+l"(d) : "l"(a), "l"(b));
}
__device__ __forceinline__ float2 up(u64 v){
    float2 r; asm("mov.b64 {%0,%1},%2;" : "=f"(r.x), "=f"(r.y) : "l"(v)); return r;
}
__device__ __forceinline__ float sigf(float x){ return 1.0f/(1.0f + expf(-x)); }

// ---------------- init ----------------
__global__ void init_state(){
    int i = blockIdx.x*blockDim.x + threadIdx.x;
    if (i < BB*HH){ g_h[i]=0.0f; g_c[i]=0.0f; }
    if (i < BB) g_tok[i] = 127;
}

// =====================================================================
// Encoder gate partials: gates = e@enc_wx + h@enc_wh  (3 slices of 512)
// grid (8 colblk, 8 bgroup, 3 slice) x 128 thr. Thread: 4 cols x 4 batches.
// =====================================================================
__global__ __launch_bounds__(128) void enc_gates(
    const int* __restrict__ x, const float* __restrict__ emb,
    const float* __restrict__ wx, const float* __restrict__ wh, int t)
{
    int colblk = blockIdx.x, bg = blockIdx.y, s = blockIdx.z;
    int b0 = bg*4;
    __shared__ float4 sA[512];

    if (s == 0){
        int t0 = x[(b0+0)*LL+t]*EE, t1 = x[(b0+1)*LL+t]*EE;
        int t2 = x[(b0+2)*LL+t]*EE, t3 = x[(b0+3)*LL+t]*EE;
        for (int k=threadIdx.x; k<512; k+=128){
            float4 v; v.x=emb[t0+k]; v.y=emb[t1+k]; v.z=emb[t2+k]; v.w=emb[t3+k];
            sA[k]=v;
        }
    } else {
        int off = (s-1)*512;
        for (int k=threadIdx.x; k<512; k+=128){
            float4 v;
            v.x=g_h[(b0+0)*HH+off+k]; v.y=g_h[(b0+1)*HH+off+k];
            v.z=g_h[(b0+2)*HH+off+k]; v.w=g_h[(b0+3)*HH+off+k];
            sA[k]=v;
        }
    }
    __syncthreads();

    const float* w = (s==0) ? wx : (wh + (size_t)(s-1)*512*G4);
    int j0 = colblk*512 + threadIdx.x*4;
    u64 A00=0,A01=0,A10=0,A11=0,A20=0,A21=0,A30=0,A31=0;

    #pragma unroll 4
    for (int k=0;k<512;k++){
        float4 wv = *(const float4*)(w + (size_t)k*G4 + j0);
        float4 av = sA[k];
        u64 alo = pk(av.x,av.y), ahi = pk(av.z,av.w);
        u64 w0=pk(wv.x,wv.x), w1=pk(wv.y,wv.y), w2=pk(wv.z,wv.z), w3=pk(wv.w,wv.w);
        fma2(A00,w0,alo); fma2(A01,w0,ahi);
        fma2(A10,w1,alo); fma2(A11,w1,ahi);
        fma2(A20,w2,alo); fma2(A21,w2,ahi);
        fma2(A30,w3,alo); fma2(A31,w3,ahi);
    }
    float2 p00=up(A00),p10=up(A10),p20=up(A20),p30=up(A30);
    float2 p01=up(A01),p11=up(A11),p21=up(A21),p31=up(A31);
    float* pp = g_part + (size_t)s*BB*G4 + j0;
    *(float4*)(pp + (size_t)(b0+0)*G4) = make_float4(p00.x,p10.x,p20.x,p30.x);
    *(float4*)(pp + (size_t)(b0+1)*G4) = make_float4(p00.y,p10.y,p20.y,p30.y);
    *(float4*)(pp + (size_t)(b0+2)*G4) = make_float4(p01.x,p11.x,p21.x,p31.x);
    *(float4*)(pp + (size_t)(b0+3)*G4) = make_float4(p01.y,p11.y,p21.y,p31.y);
}

// =====================================================================
// Decoder gate partials: gates = inp@dec_wx + h@dec_wh (4 slices of 512)
// =====================================================================
__global__ __launch_bounds__(128) void dec_gates(
    const float* __restrict__ dwx, const float* __restrict__ dwh)
{
    int colblk = blockIdx.x, bg = blockIdx.y, s = blockIdx.z;
    int b0 = bg*4;
    __shared__ float4 sA[512];

    const float* act = (s<2) ? g_inp : g_h;
    int off = (s&1)*512;
    for (int k=threadIdx.x; k<512; k+=128){
        float4 v;
        v.x=act[(b0+0)*HH+off+k]; v.y=act[(b0+1)*HH+off+k];
        v.z=act[(b0+2)*HH+off+k]; v.w=act[(b0+3)*HH+off+k];
        sA[k]=v;
    }
    __syncthreads();

    const float* w = (s<2) ? (dwx + (size_t)s*512*G4) : (dwh + (size_t)(s-2)*512*G4);
    int j0 = colblk*512 + threadIdx.x*4;
    u64 A00=0,A01=0,A10=0,A11=0,A20=0,A21=0,A30=0,A31=0;

    #pragma unroll 4
    for (int k=0;k<512;k++){
        float4 wv = *(const float4*)(w + (size_t)k*G4 + j0);
        float4 av = sA[k];
        u64 alo = pk(av.x,av.y), ahi = pk(av.z,av.w);
        u64 w0=pk(wv.x,wv.x), w1=pk(wv.y,wv.y), w2=pk(wv.z,wv.z), w3=pk(wv.w,wv.w);
        fma2(A00,w0,alo); fma2(A01,w0,ahi);
        fma2(A10,w1,alo); fma2(A11,w1,ahi);
        fma2(A20,w2,alo); fma2(A21,w2,ahi);
        fma2(A30,w3,alo); fma2(A31,w3,ahi);
    }
    float2 p00=up(A00),p10=up(A10),p20=up(A20),p30=up(A30);
    float2 p01=up(A01),p11=up(A11),p21=up(A21),p31=up(A31);
    float* pp = g_part + (size_t)s*BB*G4 + j0;
    *(float4*)(pp + (size_t)(b0+0)*G4) = make_float4(p00.x,p10.x,p20.x,p30.x);
    *(float4*)(pp + (size_t)(b0+1)*G4) = make_float4(p00.y,p10.y,p20.y,p30.y);
    *(float4*)(pp + (size_t)(b0+2)*G4) = make_float4(p01.x,p11.x,p21.x,p31.x);
    *(float4*)(pp + (size_t)(b0+3)*G4) = make_float4(p01.y,p11.y,p21.y,p31.y);
}

// =====================================================================
// Combine partials + LSTM cell update (gate order i,f,g,o)
// =====================================================================
__global__ __launch_bounds__(256) void lstm_update(
    const float* __restrict__ bias, int nS, int isEnc, int t)
{
    int idx = blockIdx.x*blockDim.x + threadIdx.x;   // b*HH + d
    if (idx >= BB*HH) return;
    int b = idx >> 10, d = idx & (HH-1);
    float gi = bias[d], gf = bias[HH+d], gg = bias[2*HH+d], go = bias[3*HH+d];
    for (int s=0;s<nS;s++){
        const float* p = g_part + (size_t)(s*BB + b)*G4;
        gi += p[d]; gf += p[HH+d]; gg += p[2*HH+d]; go += p[3*HH+d];
    }
    float c = g_c[idx];
    c = sigf(gf)*c + sigf(gi)*tanhf(gg);
    float h = sigf(go)*tanhf(c);
    g_c[idx] = c; g_h[idx] = h;
    if (isEnc) g_enc[((size_t)t*BB + b)*HH + d] = h;
}

// =====================================================================
// Decoder attention: e = dec_embed[tok]; softmax([e,h]@attn_w + b); ctx
// one block per batch row
// =====================================================================
__global__ __launch_bounds__(128) void attn_ctx(
    const float* __restrict__ demb, const float* __restrict__ aw,
    const float* __restrict__ ab)
{
    int b = blockIdx.x;
    __shared__ float sE[HH], sH[HH], sP[2][64], sS[64];
    int tok = g_tok[b];
    for (int k=threadIdx.x; k<HH; k+=128){
        float e = demb[(size_t)tok*HH + k];
        sE[k]=e; g_e[b*HH+k]=e;
        sH[k]=g_h[b*HH+k];
    }
    __syncthreads();

    {   // scores: half 0 uses e vs rows [0,1024), half 1 uses h vs rows [1024,2048)
        int l = threadIdx.x & 63, half = threadIdx.x >> 6;
        const float* src = half ? sH : sE;
        const float* wb  = aw + (size_t)half*HH*64;
        float a0=0.f,a1=0.f,a2=0.f,a3=0.f;
        #pragma unroll 4
        for (int k=0;k<HH;k+=4){
            a0 += src[k+0]*wb[(k+0)*64 + l];
            a1 += src[k+1]*wb[(k+1)*64 + l];
            a2 += src[k+2]*wb[(k+2)*64 + l];
            a3 += src[k+3]*wb[(k+3)*64 + l];
        }
        sP[half][l] = (a0+a1)+(a2+a3);
    }
    __syncthreads();
    if (threadIdx.x == 0){
        float sv[64]; float m = -INFINITY;
        for (int i=0;i<64;i++){ float v = sP[0][i]+sP[1][i]+ab[i]; sv[i]=v; m = fmaxf(m,v); }
        float sum = 0.0f;
        for (int i=0;i<64;i++){ float e = expf(sv[i]-m); sS[i]=e; sum += e; }
        float inv = 1.0f/sum;
        for (int i=0;i<64;i++) sS[i] *= inv;
    }
    __syncthreads();
    for (int d=threadIdx.x; d<HH; d+=128){
        float acc = 0.0f;
        #pragma unroll
        for (int l=0;l<64;l++) acc += sS[l]*g_enc[((size_t)l*BB + b)*HH + d];
        g_ctx[b*HH+d] = acc;
    }
}

// =====================================================================
// comb partials: [e,ctx] @ comb_w   (4 slices of 512, out cols = 1024)
// grid (2, 8, 4) x 128
// =====================================================================
__global__ __launch_bounds__(128) void comb_part(const float* __restrict__ cw)
{
    int colblk = blockIdx.x, bg = blockIdx.y, s = blockIdx.z;
    int b0 = bg*4;
    __shared__ float4 sA[512];
    const float* act = (s<2) ? g_e : g_ctx;
    int off = (s&1)*512;
    for (int k=threadIdx.x; k<512; k+=128){
        float4 v;
        v.x=act[(b0+0)*HH+off+k]; v.y=act[(b0+1)*HH+off+k];
        v.z=act[(b0+2)*HH+off+k]; v.w=act[(b0+3)*HH+off+k];
        sA[k]=v;
    }
    __syncthreads();
    const float* w = cw + (size_t)s*512*HH;
    int j0 = colblk*512 + threadIdx.x*4;
    u64 A00=0,A01=0,A10=0,A11=0,A20=0,A21=0,A30=0,A31=0;
    #pragma unroll 4
    for (int k=0;k<512;k++){
        float4 wv = *(const float4*)(w + (size_t)k*HH + j0);
        float4 av = sA[k];
        u64 alo = pk(av.x,av.y), ahi = pk(av.z,av.w);
        u64 w0=pk(wv.x,wv.x), w1=pk(wv.y,wv.y), w2=pk(wv.z,wv.z), w3=pk(wv.w,wv.w);
        fma2(A00,w0,alo); fma2(A01,w0,ahi);
        fma2(A10,w1,alo); fma2(A11,w1,ahi);
        fma2(A20,w2,alo); fma2(A21,w2,ahi);
        fma2(A30,w3,alo); fma2(A31,w3,ahi);
    }
    float2 p00=up(A00),p10=up(A10),p20=up(A20),p30=up(A30);
    float2 p01=up(A01),p11=up(A11),p21=up(A21),p31=up(A31);
    float* pp = g_part2 + (size_t)s*BB*HH + j0;
    *(float4*)(pp + (size_t)(b0+0)*HH) = make_float4(p00.x,p10.x,p20.x,p30.x);
    *(float4*)(pp + (size_t)(b0+1)*HH) = make_float4(p00.y,p10.y,p20.y,p30.y);
    *(float4*)(pp + (size_t)(b0+2)*HH) = make_float4(p01.x,p11.x,p21.x,p31.x);
    *(float4*)(pp + (size_t)(b0+3)*HH) = make_float4(p01.y,p11.y,p21.y,p31.y);
}

__global__ __launch_bounds__(256) void comb_fin(const float* __restrict__ cb)
{
    int idx = blockIdx.x*blockDim.x + threadIdx.x;
    if (idx >= BB*HH) return;
    int b = idx >> 10, j = idx & (HH-1);
    float v = cb[j];
    for (int s=0;s<4;s++) v += g_part2[(size_t)(s*BB + b)*HH + j];
    g_inp[idx] = fmaxf(v, 0.0f);
}

// =====================================================================
// Output projection: logits[b][v] = h[b] . out_w[:,v] + out_b[v]
// smem-tiled GEMM, 32 b x 128 v per block. grid 250 x 256 thr.
// =====================================================================
__global__ __launch_bounds__(256) void out_proj(
    const float* __restrict__ W, const float* __restrict__ ob,
    float* __restrict__ out, int t)
{
    __shared__ float sW[32*128];
    __shared__ float sHh[32*36];     // [kk][b], padded stride 36
    int v0 = blockIdx.x*128;
    int tb = threadIdx.x >> 5, tv = threadIdx.x & 31;
    int b0 = tb*4, vl = tv*4;

    float4 bv = *(const float4*)(ob + v0 + vl);
    u64 b01 = pk(bv.x,bv.y), b23 = pk(bv.z,bv.w);
    u64 A00=b01,A01=b23,A10=b01,A11=b23,A20=b01,A21=b23,A30=b01,A31=b23;

    for (int k0=0;k0<HH;k0+=32){
        for (int i=threadIdx.x;i<4096;i+=256){
            int kk=i>>7, vv=i&127;
            sW[i] = W[(size_t)(k0+kk)*VV + v0 + vv];
        }
        for (int i=threadIdx.x;i<1024;i+=256){
            int bb=i>>5, kk=i&31;
            sHh[kk*36+bb] = g_h[bb*HH + k0 + kk];
        }
        __syncthreads();
        #pragma unroll 8
        for (int kk=0;kk<32;kk++){
            float4 w = *(float4*)&sW[kk*128 + vl];
            u64 w01 = pk(w.x,w.y), w23 = pk(w.z,w.w);
            float4 a = *(float4*)&sHh[kk*36 + b0];
            u64 s0=pk(a.x,a.x), s1=pk(a.y,a.y), s2=pk(a.z,a.z), s3=pk(a.w,a.w);
            fma2(A00,s0,w01); fma2(A01,s0,w23);
            fma2(A10,s1,w01); fma2(A11,s1,w23);
            fma2(A20,s2,w01); fma2(A21,s2,w23);
            fma2(A30,s3,w01); fma2(A31,s3,w23);
        }
        __syncthreads();
    }
    float2 r0a=up(A00), r0b=up(A01);
    float2 r1a=up(A10), r1b=up(A11);
    float2 r2a=up(A20), r2b=up(A21);
    float2 r3a=up(A30), r3b=up(A31);
    *(float4*)(out + ((size_t)(b0+0)*LL + t)*VV + v0+vl) = make_float4(r0a.x,r0a.y,r0b.x,r0b.y);
    *(float4*)(out + ((size_t)(b0+1)*LL + t)*VV + v0+vl) = make_float4(r1a.x,r1a.y,r1b.x,r1b.y);
    *(float4*)(out + ((size_t)(b0+2)*LL + t)*VV + v0+vl) = make_float4(r2a.x,r2a.y,r2b.x,r2b.y);
    *(float4*)(out + ((size_t)(b0+3)*LL + t)*VV + v0+vl) = make_float4(r3a.x,r3a.y,r3b.x,r3b.y);
}

// =====================================================================
// log_softmax in-place + argmax (first-occurrence, matching jnp.argmax)
// =====================================================================
__global__ __launch_bounds__(256) void lsm_argmax(float* __restrict__ out, int t)
{
    int b = blockIdx.x;
    float* row = out + ((size_t)b*LL + t)*VV;
    __shared__ float sm[256];
    __shared__ int   si[256];

    float m = -INFINITY; int mi = 0;
    for (int v=threadIdx.x; v<VV; v+=256){
        float xv = row[v];
        if (xv > m){ m = xv; mi = v; }
    }
    sm[threadIdx.x]=m; si[threadIdx.x]=mi;
    __syncthreads();
    for (int st=128; st>0; st>>=1){
        if (threadIdx.x < st){
            float m2=sm[threadIdx.x+st]; int i2=si[threadIdx.x+st];
            if (m2 > sm[threadIdx.x] || (m2==sm[threadIdx.x] && i2 < si[threadIdx.x])){
                sm[threadIdx.x]=m2; si[threadIdx.x]=i2;
            }
        }
        __syncthreads();
    }
    float gm = sm[0];
    if (threadIdx.x==0) g_tok[b]=si[0];
    __syncthreads();

    float s = 0.0f;
    for (int v=threadIdx.x; v<VV; v+=256) s += expf(row[v]-gm);
    sm[threadIdx.x]=s;
    __syncthreads();
    for (int st=128; st>0; st>>=1){
        if (threadIdx.x < st) sm[threadIdx.x] += sm[threadIdx.x+st];
        __syncthreads();
    }
    float lse = gm + logf(sm[0]);
    for (int v=threadIdx.x; v<VV; v+=256) row[v] -= lse;
}

// =====================================================================
extern "C" void kernel_launch(void* const* d_in, const int* in_sizes, int n_in,
                              void* d_out, int out_size)
{
    const int*   x    = (const int*)  d_in[0];
    const float* eemb = (const float*)d_in[1];
    const float* ewx  = (const float*)d_in[2];
    const float* ewh  = (const float*)d_in[3];
    const float* eb   = (const float*)d_in[4];
    const float* demb = (const float*)d_in[5];
    const float* aw   = (const float*)d_in[6];
    const float* ab   = (const float*)d_in[7];
    const float* cw   = (const float*)d_in[8];
    const float* cb   = (const float*)d_in[9];
    const float* dwx  = (const float*)d_in[10];
    const float* dwh  = (const float*)d_in[11];
    const float* db   = (const float*)d_in[12];
    const float* ow   = (const float*)d_in[13];
    const float* obb  = (const float*)d_in[14];
    float* out = (float*)d_out;

    // ---- encoder ----
    init_state<<<128,256>>>();
    for (int t=0;t<LL;t++){
        enc_gates<<<dim3(8,8,3),128>>>(x, eemb, ewx, ewh, t);
        lstm_update<<<128,256>>>(eb, 3, 1, t);
    }

    // ---- decoder (reset h,c,tok) ----
    init_state<<<128,256>>>();
    for (int t=0;t<LL;t++){
        attn_ctx<<<BB,128>>>(demb, aw, ab);
        comb_part<<<dim3(2,8,4),128>>>(cw);
        comb_fin<<<128,256>>>(cb);
        dec_gates<<<dim3(8,8,4),128>>>(dwx, dwh);
        lstm_update<<<128,256>>>(db, 4, 0, 0);
        out_proj<<<250,256>>>(ow, obb, out, t);
        lsm_argmax<<<BB,256>>>(out, t);
    }
}

// round 4
// speedup vs baseline: 1.9710x; 1.9710x over previous
#include <cuda_runtime.h>
#include <math.h>
#include <cstdint>

#define BB 32
#define EE 512
#define HH 1024
#define G4 4096
#define LL 64
#define VV 32000

typedef unsigned long long u64;

// ---------------- device scratch (no allocations allowed) ----------------
__device__ float g_h[BB*HH];
__device__ float g_hT[HH*BB];          // transposed h for out_proj tiles
__device__ float g_c[BB*HH];
__device__ float g_enc[LL*BB*HH];      // [l][b][d]
__device__ float g_e[BB*HH];           // decoder embedding
__device__ float g_ctx[BB*HH];
__device__ float g_inp[BB*HH];
__device__ float g_part[8*BB*G4];      // split-K partials for LSTM gates
__device__ float g_part2[8*BB*HH];     // split-K partials for comb
__device__ int   g_tok[BB];

// ---------------- f32x2 packed helpers (FFMA2 path) ----------------
__device__ __forceinline__ u64 pk(float x, float y){
    u64 r; asm("mov.b64 %0,{%1,%2};" : "=l"(r) : "f"(x), "f"(y)); return r;
}
__device__ __forceinline__ void fma2(u64 &d, u64 a, u64 b){
    asm("fma.rn.f32x2 %0, %1, %2, %0;" : "+l"(d) : "l"(a), "l"(b));
}
__device__ __forceinline__ float2 up(u64 v){
    float2 r; asm("mov.b64 {%0,%1},%2;" : "=f"(r.x), "=f"(r.y) : "l"(v)); return r;
}
__device__ __forceinline__ float sigf(float x){ return 1.0f/(1.0f + expf(-x)); }

__device__ __forceinline__ void cpa16(void* s, const void* g){
    uint32_t sa = (uint32_t)__cvta_generic_to_shared(s);
    asm volatile("cp.async.cg.shared.global [%0], [%1], 16;" :: "r"(sa), "l"(g));
}
#define CP_COMMIT asm volatile("cp.async.commit_group;")
#define CP_WAIT0  asm volatile("cp.async.wait_group 0;")

// ---------------- init ----------------
__global__ void init_state(){
    int i = blockIdx.x*blockDim.x + threadIdx.x;
    if (i < BB*HH){ g_h[i]=0.0f; g_c[i]=0.0f; }
    if (i < BB) g_tok[i] = 127;
}

// =====================================================================
// Encoder gate partials: gates = e@enc_wx + h@enc_wh
// K split into 6 slices of 256 (2 emb + 4 h). grid (8,8,6) x 128.
// Thread: 4 cols x 4 batches, 8-deep load batching for MLP.
// =====================================================================
__global__ __launch_bounds__(128) void enc_gates(
    const int* __restrict__ x, const float* __restrict__ emb,
    const float* __restrict__ wx, const float* __restrict__ wh, int t)
{
    int colblk = blockIdx.x, bg = blockIdx.y, s = blockIdx.z;
    int b0 = bg*4;
    __shared__ float4 sA[256];

    if (s < 2){
        int off = s*256;
        int t0 = x[(b0+0)*LL+t]*EE+off, t1 = x[(b0+1)*LL+t]*EE+off;
        int t2 = x[(b0+2)*LL+t]*EE+off, t3 = x[(b0+3)*LL+t]*EE+off;
        for (int k=threadIdx.x; k<256; k+=128)
            sA[k] = make_float4(emb[t0+k], emb[t1+k], emb[t2+k], emb[t3+k]);
    } else {
        int off = (s-2)*256;
        for (int k=threadIdx.x; k<256; k+=128)
            sA[k] = make_float4(g_h[(b0+0)*HH+off+k], g_h[(b0+1)*HH+off+k],
                                g_h[(b0+2)*HH+off+k], g_h[(b0+3)*HH+off+k]);
    }
    __syncthreads();

    const float* w = (s<2) ? (wx + (size_t)s*256*G4) : (wh + (size_t)(s-2)*256*G4);
    int j0 = colblk*512 + threadIdx.x*4;
    u64 A00=0,A01=0,A10=0,A11=0,A20=0,A21=0,A30=0,A31=0;

    for (int k0=0;k0<256;k0+=8){
        float4 wv[8];
        #pragma unroll
        for (int u=0;u<8;u++) wv[u] = *(const float4*)(w + (size_t)(k0+u)*G4 + j0);
        #pragma unroll
        for (int u=0;u<8;u++){
            float4 av = sA[k0+u];
            u64 alo = pk(av.x,av.y), ahi = pk(av.z,av.w);
            u64 w0=pk(wv[u].x,wv[u].x), w1=pk(wv[u].y,wv[u].y);
            u64 w2=pk(wv[u].z,wv[u].z), w3=pk(wv[u].w,wv[u].w);
            fma2(A00,w0,alo); fma2(A01,w0,ahi);
            fma2(A10,w1,alo); fma2(A11,w1,ahi);
            fma2(A20,w2,alo); fma2(A21,w2,ahi);
            fma2(A30,w3,alo); fma2(A31,w3,ahi);
        }
    }
    float2 p00=up(A00),p10=up(A10),p20=up(A20),p30=up(A30);
    float2 p01=up(A01),p11=up(A11),p21=up(A21),p31=up(A31);
    float* pp = g_part + (size_t)s*BB*G4 + j0;
    *(float4*)(pp + (size_t)(b0+0)*G4) = make_float4(p00.x,p10.x,p20.x,p30.x);
    *(float4*)(pp + (size_t)(b0+1)*G4) = make_float4(p00.y,p10.y,p20.y,p30.y);
    *(float4*)(pp + (size_t)(b0+2)*G4) = make_float4(p01.x,p11.x,p21.x,p31.x);
    *(float4*)(pp + (size_t)(b0+3)*G4) = make_float4(p01.y,p11.y,p21.y,p31.y);
}

// =====================================================================
// Decoder gate partials: gates = inp@dec_wx + h@dec_wh (8 slices of 256)
// grid (8,8,8) x 128
// =====================================================================
__global__ __launch_bounds__(128) void dec_gates(
    const float* __restrict__ dwx, const float* __restrict__ dwh)
{
    int colblk = blockIdx.x, bg = blockIdx.y, s = blockIdx.z;
    int b0 = bg*4;
    __shared__ float4 sA[256];

    const float* act = (s<4) ? g_inp : g_h;
    int off = (s&3)*256;
    for (int k=threadIdx.x; k<256; k+=128)
        sA[k] = make_float4(act[(b0+0)*HH+off+k], act[(b0+1)*HH+off+k],
                            act[(b0+2)*HH+off+k], act[(b0+3)*HH+off+k]);
    __syncthreads();

    const float* w = (s<4) ? (dwx + (size_t)s*256*G4) : (dwh + (size_t)(s-4)*256*G4);
    int j0 = colblk*512 + threadIdx.x*4;
    u64 A00=0,A01=0,A10=0,A11=0,A20=0,A21=0,A30=0,A31=0;

    for (int k0=0;k0<256;k0+=8){
        float4 wv[8];
        #pragma unroll
        for (int u=0;u<8;u++) wv[u] = *(const float4*)(w + (size_t)(k0+u)*G4 + j0);
        #pragma unroll
        for (int u=0;u<8;u++){
            float4 av = sA[k0+u];
            u64 alo = pk(av.x,av.y), ahi = pk(av.z,av.w);
            u64 w0=pk(wv[u].x,wv[u].x), w1=pk(wv[u].y,wv[u].y);
            u64 w2=pk(wv[u].z,wv[u].z), w3=pk(wv[u].w,wv[u].w);
            fma2(A00,w0,alo); fma2(A01,w0,ahi);
            fma2(A10,w1,alo); fma2(A11,w1,ahi);
            fma2(A20,w2,alo); fma2(A21,w2,ahi);
            fma2(A30,w3,alo); fma2(A31,w3,ahi);
        }
    }
    float2 p00=up(A00),p10=up(A10),p20=up(A20),p30=up(A30);
    float2 p01=up(A01),p11=up(A11),p21=up(A21),p31=up(A31);
    float* pp = g_part + (size_t)s*BB*G4 + j0;
    *(float4*)(pp + (size_t)(b0+0)*G4) = make_float4(p00.x,p10.x,p20.x,p30.x);
    *(float4*)(pp + (size_t)(b0+1)*G4) = make_float4(p00.y,p10.y,p20.y,p30.y);
    *(float4*)(pp + (size_t)(b0+2)*G4) = make_float4(p01.x,p11.x,p21.x,p31.x);
    *(float4*)(pp + (size_t)(b0+3)*G4) = make_float4(p01.y,p11.y,p21.y,p31.y);
}

// =====================================================================
// Combine partials + LSTM cell update (gate order i,f,g,o); writes g_hT too
// =====================================================================
template<int NS>
__global__ __launch_bounds__(256) void lstm_update(
    const float* __restrict__ bias, int isEnc, int t)
{
    int idx = blockIdx.x*blockDim.x + threadIdx.x;   // b*HH + d
    if (idx >= BB*HH) return;
    int b = idx >> 10, d = idx & (HH-1);
    float gi = bias[d], gf = bias[HH+d], gg = bias[2*HH+d], go = bias[3*HH+d];
    #pragma unroll
    for (int s=0;s<NS;s++){
        const float* p = g_part + (size_t)(s*BB + b)*G4;
        gi += p[d]; gf += p[HH+d]; gg += p[2*HH+d]; go += p[3*HH+d];
    }
    float c = g_c[idx];
    c = sigf(gf)*c + sigf(gi)*tanhf(gg);
    float h = sigf(go)*tanhf(c);
    g_c[idx] = c; g_h[idx] = h;
    g_hT[d*BB + b] = h;
    if (isEnc) g_enc[((size_t)t*BB + b)*HH + d] = h;
}

// =====================================================================
// Decoder attention: e = dec_embed[tok]; softmax([e,h]@attn_w + b); ctx
// one block of 256 per batch row; scores computed with 4-way K split
// =====================================================================
__global__ __launch_bounds__(256) void attn_ctx(
    const float* __restrict__ demb, const float* __restrict__ aw,
    const float* __restrict__ ab)
{
    int b = blockIdx.x, tid = threadIdx.x;
    __shared__ float sE[HH], sH2[HH], sPP[4][64], sS[64];
    int tok = g_tok[b];
    for (int k=tid; k<HH; k+=256){
        float e = demb[(size_t)tok*HH + k];
        sE[k]=e; g_e[b*HH+k]=e;
        sH2[k]=g_h[b*HH+k];
    }
    __syncthreads();

    {   // scores: q selects 512-row chunk of attn_w, l the output column
        int l = tid & 63, q = tid >> 6;
        const float* src = (q<2) ? (sE + q*512) : (sH2 + (q-2)*512);
        const float* wb  = aw + (size_t)q*512*64;
        float a0=0.f,a1=0.f,a2=0.f,a3=0.f;
        #pragma unroll 4
        for (int k=0;k<512;k+=4){
            a0 += src[k+0]*wb[(k+0)*64 + l];
            a1 += src[k+1]*wb[(k+1)*64 + l];
            a2 += src[k+2]*wb[(k+2)*64 + l];
            a3 += src[k+3]*wb[(k+3)*64 + l];
        }
        sPP[q][l] = (a0+a1)+(a2+a3);
    }
    __syncthreads();
    if (tid == 0){
        float sv[64]; float m = -INFINITY;
        for (int i=0;i<64;i++){
            float v = sPP[0][i]+sPP[1][i]+sPP[2][i]+sPP[3][i]+ab[i];
            sv[i]=v; m = fmaxf(m,v);
        }
        float sum = 0.0f;
        for (int i=0;i<64;i++){ float e = expf(sv[i]-m); sS[i]=e; sum += e; }
        float inv = 1.0f/sum;
        for (int i=0;i<64;i++) sS[i] *= inv;
    }
    __syncthreads();
    {   // ctx: each thread 4 contiguous d
        int d = tid*4;
        float ax=0.f, ay=0.f, az=0.f, awc=0.f;
        #pragma unroll 4
        for (int l=0;l<64;l++){
            float s = sS[l];
            float4 ev = *(const float4*)&g_enc[((size_t)l*BB + b)*HH + d];
            ax += s*ev.x; ay += s*ev.y; az += s*ev.z; awc += s*ev.w;
        }
        *(float4*)&g_ctx[b*HH + d] = make_float4(ax,ay,az,awc);
    }
}

// =====================================================================
// comb partials: [e,ctx] @ comb_w   (8 slices of 256, out cols = 1024)
// grid (2, 8, 8) x 128
// =====================================================================
__global__ __launch_bounds__(128) void comb_part(const float* __restrict__ cw)
{
    int colblk = blockIdx.x, bg = blockIdx.y, s = blockIdx.z;
    int b0 = bg*4;
    __shared__ float4 sA[256];
    const float* act = (s<4) ? g_e : g_ctx;
    int off = (s&3)*256;
    for (int k=threadIdx.x; k<256; k+=128)
        sA[k] = make_float4(act[(b0+0)*HH+off+k], act[(b0+1)*HH+off+k],
                            act[(b0+2)*HH+off+k], act[(b0+3)*HH+off+k]);
    __syncthreads();
    const float* w = cw + (size_t)s*256*HH;
    int j0 = colblk*512 + threadIdx.x*4;
    u64 A00=0,A01=0,A10=0,A11=0,A20=0,A21=0,A30=0,A31=0;
    for (int k0=0;k0<256;k0+=8){
        float4 wv[8];
        #pragma unroll
        for (int u=0;u<8;u++) wv[u] = *(const float4*)(w + (size_t)(k0+u)*HH + j0);
        #pragma unroll
        for (int u=0;u<8;u++){
            float4 av = sA[k0+u];
            u64 alo = pk(av.x,av.y), ahi = pk(av.z,av.w);
            u64 w0=pk(wv[u].x,wv[u].x), w1=pk(wv[u].y,wv[u].y);
            u64 w2=pk(wv[u].z,wv[u].z), w3=pk(wv[u].w,wv[u].w);
            fma2(A00,w0,alo); fma2(A01,w0,ahi);
            fma2(A10,w1,alo); fma2(A11,w1,ahi);
            fma2(A20,w2,alo); fma2(A21,w2,ahi);
            fma2(A30,w3,alo); fma2(A31,w3,ahi);
        }
    }
    float2 p00=up(A00),p10=up(A10),p20=up(A20),p30=up(A30);
    float2 p01=up(A01),p11=up(A11),p21=up(A21),p31=up(A31);
    float* pp = g_part2 + (size_t)s*BB*HH + j0;
    *(float4*)(pp + (size_t)(b0+0)*HH) = make_float4(p00.x,p10.x,p20.x,p30.x);
    *(float4*)(pp + (size_t)(b0+1)*HH) = make_float4(p00.y,p10.y,p20.y,p30.y);
    *(float4*)(pp + (size_t)(b0+2)*HH) = make_float4(p01.x,p11.x,p21.x,p31.x);
    *(float4*)(pp + (size_t)(b0+3)*HH) = make_float4(p01.y,p11.y,p21.y,p31.y);
}

__global__ __launch_bounds__(256) void comb_fin(const float* __restrict__ cb)
{
    int idx = blockIdx.x*blockDim.x + threadIdx.x;
    if (idx >= BB*HH) return;
    int b = idx >> 10, j = idx & (HH-1);
    float v = cb[j];
    #pragma unroll
    for (int s=0;s<8;s++) v += g_part2[(size_t)(s*BB + b)*HH + j];
    g_inp[idx] = fmaxf(v, 0.0f);
}

// =====================================================================
// Output projection: logits[b][v] = h[b] . out_w[:,v] + out_b[v]
// cp.async double-buffered smem pipeline. 32b x 128v per block. grid 250.
// =====================================================================
__global__ __launch_bounds__(256) void out_proj(
    const float* __restrict__ W, const float* __restrict__ ob,
    float* __restrict__ out, int t)
{
    __shared__ float sW[2][32*128];
    __shared__ float sH[2][32*32];
    int v0 = blockIdx.x*128;
    int tid = threadIdx.x;
    int tb = tid >> 5, tv = tid & 31;
    int b0 = tb*4, vl = tv*4;

    // prologue: async-load tile 0
    {
        const float* Wg = W + v0;
        for (int i=tid;i<1024;i+=256){
            int row=i>>5, col=(i&31)*4;
            cpa16(&sW[0][row*128+col], Wg + (size_t)row*VV + col);
        }
        cpa16(&sH[0][tid*4], g_hT + tid*4);
        CP_COMMIT;
    }

    float4 bv = *(const float4*)(ob + v0 + vl);
    u64 b01 = pk(bv.x,bv.y), b23 = pk(bv.z,bv.w);
    u64 A00=b01,A01=b23,A10=b01,A11=b23,A20=b01,A21=b23,A30=b01,A31=b23;

    int buf = 0;
    for (int kt=0;kt<32;kt++){
        CP_WAIT0;
        __syncthreads();
        if (kt < 31){
            int k0 = (kt+1)*32;
            const float* Wg = W + (size_t)k0*VV + v0;
            for (int i=tid;i<1024;i+=256){
                int row=i>>5, col=(i&31)*4;
                cpa16(&sW[buf^1][row*128+col], Wg + (size_t)row*VV + col);
            }
            cpa16(&sH[buf^1][tid*4], g_hT + k0*32 + tid*4);
            CP_COMMIT;
        }
        const float* pw = sW[buf];
        const float* ph = sH[buf];
        #pragma unroll 8
        for (int kk=0;kk<32;kk++){
            float4 w = *(const float4*)(pw + kk*128 + vl);
            u64 w01 = pk(w.x,w.y), w23 = pk(w.z,w.w);
            float4 a = *(const float4*)(ph + kk*32 + b0);
            u64 s0=pk(a.x,a.x), s1=pk(a.y,a.y), s2=pk(a.z,a.z), s3=pk(a.w,a.w);
            fma2(A00,s0,w01); fma2(A01,s0,w23);
            fma2(A10,s1,w01); fma2(A11,s1,w23);
            fma2(A20,s2,w01); fma2(A21,s2,w23);
            fma2(A30,s3,w01); fma2(A31,s3,w23);
        }
        buf ^= 1;
    }
    float2 r0a=up(A00), r0b=up(A01);
    float2 r1a=up(A10), r1b=up(A11);
    float2 r2a=up(A20), r2b=up(A21);
    float2 r3a=up(A30), r3b=up(A31);
    *(float4*)(out + ((size_t)(b0+0)*LL + t)*VV + v0+vl) = make_float4(r0a.x,r0a.y,r0b.x,r0b.y);
    *(float4*)(out + ((size_t)(b0+1)*LL + t)*VV + v0+vl) = make_float4(r1a.x,r1a.y,r1b.x,r1b.y);
    *(float4*)(out + ((size_t)(b0+2)*LL + t)*VV + v0+vl) = make_float4(r2a.x,r2a.y,r2b.x,r2b.y);
    *(float4*)(out + ((size_t)(b0+3)*LL + t)*VV + v0+vl) = make_float4(r3a.x,r3a.y,r3b.x,r3b.y);
}

// =====================================================================
// log_softmax in-place + argmax (first-occurrence, matching jnp.argmax)
// =====================================================================
__global__ __launch_bounds__(512) void lsm_argmax(float* __restrict__ out, int t)
{
    int b = blockIdx.x, tid = threadIdx.x;
    float* row = out + ((size_t)b*LL + t)*VV;
    __shared__ float sm[512];
    __shared__ int   si[512];

    float m = -INFINITY; int mi = 0;
    for (int v=tid*4; v<VV; v+=2048){
        float4 xv = *(const float4*)(row+v);
        if (xv.x > m){ m = xv.x; mi = v; }
        if (xv.y > m){ m = xv.y; mi = v+1; }
        if (xv.z > m){ m = xv.z; mi = v+2; }
        if (xv.w > m){ m = xv.w; mi = v+3; }
    }
    sm[tid]=m; si[tid]=mi;
    __syncthreads();
    for (int st=256; st>0; st>>=1){
        if (tid < st){
            float m2=sm[tid+st]; int i2=si[tid+st];
            if (m2 > sm[tid] || (m2==sm[tid] && i2 < si[tid])){
                sm[tid]=m2; si[tid]=i2;
            }
        }
        __syncthreads();
    }
    float gm = sm[0];
    if (tid==0) g_tok[b]=si[0];
    __syncthreads();

    float s = 0.0f;
    for (int v=tid*4; v<VV; v+=2048){
        float4 xv = *(const float4*)(row+v);
        s += expf(xv.x-gm) + expf(xv.y-gm) + expf(xv.z-gm) + expf(xv.w-gm);
    }
    sm[tid]=s;
    __syncthreads();
    for (int st=256; st>0; st>>=1){
        if (tid < st) sm[tid] += sm[tid+st];
        __syncthreads();
    }
    float lse = gm + logf(sm[0]);
    for (int v=tid*4; v<VV; v+=2048){
        float4 xv = *(const float4*)(row+v);
        xv.x -= lse; xv.y -= lse; xv.z -= lse; xv.w -= lse;
        *(float4*)(row+v) = xv;
    }
}

// =====================================================================
extern "C" void kernel_launch(void* const* d_in, const int* in_sizes, int n_in,
                              void* d_out, int out_size)
{
    const int*   x    = (const int*)  d_in[0];
    const float* eemb = (const float*)d_in[1];
    const float* ewx  = (const float*)d_in[2];
    const float* ewh  = (const float*)d_in[3];
    const float* eb   = (const float*)d_in[4];
    const float* demb = (const float*)d_in[5];
    const float* aw   = (const float*)d_in[6];
    const float* ab   = (const float*)d_in[7];
    const float* cw   = (const float*)d_in[8];
    const float* cb   = (const float*)d_in[9];
    const float* dwx  = (const float*)d_in[10];
    const float* dwh  = (const float*)d_in[11];
    const float* db   = (const float*)d_in[12];
    const float* ow   = (const float*)d_in[13];
    const float* obb  = (const float*)d_in[14];
    float* out = (float*)d_out;

    // ---- encoder ----
    init_state<<<128,256>>>();
    for (int t=0;t<LL;t++){
        enc_gates<<<dim3(8,8,6),128>>>(x, eemb, ewx, ewh, t);
        lstm_update<6><<<128,256>>>(eb, 1, t);
    }

    // ---- decoder (reset h,c,tok) ----
    init_state<<<128,256>>>();
    for (int t=0;t<LL;t++){
        attn_ctx<<<BB,256>>>(demb, aw, ab);
        comb_part<<<dim3(2,8,8),128>>>(cw);
        comb_fin<<<128,256>>>(cb);
        dec_gates<<<dim3(8,8,8),128>>>(dwx, dwh);
        lstm_update<8><<<128,256>>>(db, 0, 0);
        out_proj<<<250,256>>>(ow, obb, out, t);
        lsm_argmax<<<BB,512>>>(out, t);
    }
}

// round 5
// speedup vs baseline: 4.1027x; 2.0815x over previous
#include <cuda_runtime.h>
#include <math.h>
#include <cstdint>

#define BB 32
#define EE 512
#define HH 1024
#define G4 4096
#define LL 64
#define VV 32000

typedef unsigned long long u64;

// ---------------- device scratch ----------------
__device__ __align__(16) float g_h[BB*HH];
__device__ __align__(16) float g_hT[HH*BB];        // [k][b]
__device__ __align__(16) float g_c[BB*HH];
__device__ __align__(16) float g_enc[LL*BB*HH];    // [l][b][d]
__device__ __align__(16) float g_eT[HH*BB];        // [k][b] decoder embedding
__device__ __align__(16) float g_ctxT[HH*BB];      // [k][b]
__device__ __align__(16) float g_inpT[HH*BB];      // [k][b]
__device__ __align__(16) float g_xembT[EE*BB];     // [k][b] encoder emb step t
__device__ __align__(16) float g_part[4*BB*G4];    // gate partials
__device__ __align__(16) float g_part2[16*BB*HH];  // comb partials
__device__ int g_tok[BB];

// ---------------- f32x2 packed helpers ----------------
__device__ __forceinline__ u64 pk(float x, float y){
    u64 r; asm("mov.b64 %0,{%1,%2};" : "=l"(r) : "f"(x), "f"(y)); return r;
}
__device__ __forceinline__ void fma2(u64 &d, u64 a, u64 b){
    asm("fma.rn.f32x2 %0, %1, %2, %0;" : "+l"(d) : "l"(a), "l"(b));
}
__device__ __forceinline__ float2 up(u64 v){
    float2 r; asm("mov.b64 {%0,%1},%2;" : "=f"(r.x), "=f"(r.y) : "l"(v)); return r;
}
__device__ __forceinline__ float sigf(float x){ return 1.0f/(1.0f + expf(-x)); }

__device__ __forceinline__ void cpa16(void* s, const void* g){
    uint32_t sa = (uint32_t)__cvta_generic_to_shared(s);
    asm volatile("cp.async.cg.shared.global [%0], [%1], 16;" :: "r"(sa), "l"(g));
}
#define CP_COMMIT asm volatile("cp.async.commit_group;" ::: "memory")
#define CP_WAIT(n) asm volatile("cp.async.wait_group %0;" :: "n"(n) : "memory")

// ---------------- init ----------------
__global__ void init_state(){
    int i = blockIdx.x*blockDim.x + threadIdx.x;
    if (i < BB*HH){ g_h[i]=0.0f; g_c[i]=0.0f; g_hT[i]=0.0f; }
    if (i < BB) g_tok[i] = 127;
}

// ---------------- encoder embedding gather (transposed) ----------------
__global__ __launch_bounds__(256) void gather_embT(
    const int* __restrict__ x, const float* __restrict__ emb, int t)
{
    int idx = blockIdx.x*256 + threadIdx.x;   // 16384
    int k = idx >> 5, b = idx & 31;
    g_xembT[idx] = emb[(size_t)x[b*LL+t]*EE + k];
}

// =====================================================================
// Unified split-K 2-segment GEMM: parts[slice] = A^T-tiles @ W-tiles
// A layouts: [K][32] transposed. W: [K][ldw] row-major. 16-row tiles.
// grid (ldw/128, nslices), 256 threads, 4-stage cp.async ring.
// =====================================================================
__device__ __forceinline__ void seg_resolve(
    int g, int k1u, const float* A1t, const float* W1,
    const float* A2t, const float* W2, int ldw,
    const float*& At, const float*& Wp)
{
    if (g < k1u){ At = A1t + g*16*32; Wp = W1 + (size_t)g*16*ldw; }
    else { int h = g-k1u; At = A2t + h*16*32; Wp = W2 + (size_t)h*16*ldw; }
}

__device__ __forceinline__ void load_tile16(
    int buf, int tid, const float* At, const float* Wp, int ldw, int colbase,
    float (*sW)[16*128], float (*sA)[16*32])
{
    for (int i=tid;i<512;i+=256){
        int row=i>>5, col=(i&31)*4;
        cpa16(&sW[buf][row*128+col], Wp + (size_t)row*ldw + colbase + col);
    }
    if (tid < 128){
        int row=tid>>3, col=(tid&7)*4;
        cpa16(&sA[buf][row*32+col], At + row*32 + col);
    }
    CP_COMMIT;
}

__global__ __launch_bounds__(256) void gemm_seg(
    const float* __restrict__ A1t, const float* __restrict__ W1, int k1u,
    const float* __restrict__ A2t, const float* __restrict__ W2,
    int ldw, int tpu, float* __restrict__ parts)
{
    __shared__ float sW[4][16*128];
    __shared__ float sA[4][16*32];
    int tid = threadIdx.x;
    int colbase = blockIdx.x*128;
    int slice = blockIdx.y;
    int u0 = slice*tpu;
    int tb = tid>>5, tv = tid&31;
    int b0 = tb*4, n4 = tv*4;

    #pragma unroll
    for (int p=0;p<3;p++){
        const float *At,*Wp;
        seg_resolve(u0+p, k1u, A1t,W1,A2t,W2,ldw, At,Wp);
        load_tile16(p, tid, At, Wp, ldw, colbase, sW, sA);
    }

    u64 A00=0,A01=0,A10=0,A11=0,A20=0,A21=0,A30=0,A31=0;

    for (int u=0; u<tpu; u++){
        int rem = tpu-1-u;
        if (rem >= 2) CP_WAIT(2);
        else if (rem == 1) CP_WAIT(1);
        else CP_WAIT(0);
        __syncthreads();
        if (u+3 < tpu){
            const float *At,*Wp;
            seg_resolve(u0+u+3, k1u, A1t,W1,A2t,W2,ldw, At,Wp);
            load_tile16((u+3)&3, tid, At, Wp, ldw, colbase, sW, sA);
        }
        const float* pw = sW[u&3];
        const float* pa = sA[u&3];
        #pragma unroll
        for (int kk=0;kk<16;kk++){
            float4 w = *(const float4*)(pw + kk*128 + n4);
            u64 w01 = pk(w.x,w.y), w23 = pk(w.z,w.w);
            float4 a = *(const float4*)(pa + kk*32 + b0);
            u64 s0=pk(a.x,a.x), s1=pk(a.y,a.y), s2=pk(a.z,a.z), s3=pk(a.w,a.w);
            fma2(A00,s0,w01); fma2(A01,s0,w23);
            fma2(A10,s1,w01); fma2(A11,s1,w23);
            fma2(A20,s2,w01); fma2(A21,s2,w23);
            fma2(A30,s3,w01); fma2(A31,s3,w23);
        }
    }
    float2 r0a=up(A00), r0b=up(A01);
    float2 r1a=up(A10), r1b=up(A11);
    float2 r2a=up(A20), r2b=up(A21);
    float2 r3a=up(A30), r3b=up(A31);
    float* pp = parts + (size_t)slice*BB*ldw + colbase + n4;
    *(float4*)(pp + (size_t)(b0+0)*ldw) = make_float4(r0a.x,r0a.y,r0b.x,r0b.y);
    *(float4*)(pp + (size_t)(b0+1)*ldw) = make_float4(r1a.x,r1a.y,r1b.x,r1b.y);
    *(float4*)(pp + (size_t)(b0+2)*ldw) = make_float4(r2a.x,r2a.y,r2b.x,r2b.y);
    *(float4*)(pp + (size_t)(b0+3)*ldw) = make_float4(r3a.x,r3a.y,r3b.x,r3b.y);
}

// =====================================================================
// Combine gate partials (4 slices) + LSTM cell (i,f,g,o); writes h, hT
// =====================================================================
__global__ __launch_bounds__(256) void lstm_update(
    const float* __restrict__ bias, int isEnc, int t)
{
    int idx = blockIdx.x*blockDim.x + threadIdx.x;
    if (idx >= BB*HH) return;
    int b = idx >> 10, d = idx & (HH-1);
    float gi = bias[d], gf = bias[HH+d], gg = bias[2*HH+d], go = bias[3*HH+d];
    #pragma unroll
    for (int s=0;s<4;s++){
        const float* p = g_part + (size_t)(s*BB + b)*G4;
        gi += p[d]; gf += p[HH+d]; gg += p[2*HH+d]; go += p[3*HH+d];
    }
    float c = g_c[idx];
    c = sigf(gf)*c + sigf(gi)*tanhf(gg);
    float h = sigf(go)*tanhf(c);
    g_c[idx] = c; g_h[idx] = h;
    g_hT[d*BB + b] = h;
    if (isEnc) g_enc[((size_t)t*BB + b)*HH + d] = h;
}

// =====================================================================
// Attention: e=dec_embed[tok]; softmax([e,h]@attn_w+b); ctx. Writes eT, ctxT.
// =====================================================================
__global__ __launch_bounds__(256) void attn_ctx(
    const float* __restrict__ demb, const float* __restrict__ aw,
    const float* __restrict__ ab)
{
    int b = blockIdx.x, tid = threadIdx.x;
    __shared__ float sE[HH], sH2[HH], sPP[4][64], sS[64];
    int tok = g_tok[b];
    for (int k=tid; k<HH; k+=256){
        float e = demb[(size_t)tok*HH + k];
        sE[k]=e; g_eT[k*BB+b]=e;
        sH2[k]=g_h[b*HH+k];
    }
    __syncthreads();

    {   // scores: 4-way K split over 512-row chunks of attn_w
        int l = tid & 63, q = tid >> 6;
        const float* src = (q<2) ? (sE + q*512) : (sH2 + (q-2)*512);
        const float* wb  = aw + (size_t)q*512*64;
        float a0=0.f,a1=0.f,a2=0.f,a3=0.f,a4=0.f,a5=0.f,a6=0.f,a7=0.f;
        #pragma unroll 2
        for (int k=0;k<512;k+=8){
            a0 += src[k+0]*wb[(k+0)*64 + l];
            a1 += src[k+1]*wb[(k+1)*64 + l];
            a2 += src[k+2]*wb[(k+2)*64 + l];
            a3 += src[k+3]*wb[(k+3)*64 + l];
            a4 += src[k+4]*wb[(k+4)*64 + l];
            a5 += src[k+5]*wb[(k+5)*64 + l];
            a6 += src[k+6]*wb[(k+6)*64 + l];
            a7 += src[k+7]*wb[(k+7)*64 + l];
        }
        sPP[q][l] = ((a0+a1)+(a2+a3))+((a4+a5)+(a6+a7));
    }
    __syncthreads();
    if (tid == 0){
        float sv[64]; float m = -INFINITY;
        for (int i=0;i<64;i++){
            float v = sPP[0][i]+sPP[1][i]+sPP[2][i]+sPP[3][i]+ab[i];
            sv[i]=v; m = fmaxf(m,v);
        }
        float sum = 0.0f;
        for (int i=0;i<64;i++){ float e = expf(sv[i]-m); sS[i]=e; sum += e; }
        float inv = 1.0f/sum;
        for (int i=0;i<64;i++) sS[i] *= inv;
    }
    __syncthreads();
    {   // ctx: 4 contiguous d per thread; write transposed
        int d = tid*4;
        float ax=0.f, ay=0.f, az=0.f, awc=0.f;
        #pragma unroll 8
        for (int l=0;l<64;l++){
            float s = sS[l];
            float4 ev = *(const float4*)&g_enc[((size_t)l*BB + b)*HH + d];
            ax += s*ev.x; ay += s*ev.y; az += s*ev.z; awc += s*ev.w;
        }
        g_ctxT[(d+0)*BB+b]=ax; g_ctxT[(d+1)*BB+b]=ay;
        g_ctxT[(d+2)*BB+b]=az; g_ctxT[(d+3)*BB+b]=awc;
    }
}

// =====================================================================
// comb partial reduce (16 slices) + bias + relu -> g_inpT
// =====================================================================
__global__ __launch_bounds__(256) void comb_fin(const float* __restrict__ cb)
{
    int idx = blockIdx.x*blockDim.x + threadIdx.x;
    if (idx >= BB*HH) return;
    int b = idx >> 10, j = idx & (HH-1);
    float v = cb[j];
    #pragma unroll
    for (int s=0;s<16;s++) v += g_part2[(size_t)(s*BB + b)*HH + j];
    g_inpT[j*BB + b] = fmaxf(v, 0.0f);
}

// =====================================================================
// Output projection: 4-stage cp.async ring, 16-row tiles. grid 250 x 256.
// =====================================================================
__global__ __launch_bounds__(256) void out_proj(
    const float* __restrict__ W, const float* __restrict__ ob,
    float* __restrict__ out, int t)
{
    __shared__ float sW[4][16*128];
    __shared__ float sA[4][16*32];
    int tid = threadIdx.x;
    int v0 = blockIdx.x*128;
    int tb = tid>>5, tv = tid&31;
    int b0 = tb*4, vl = tv*4;

    #pragma unroll
    for (int p=0;p<3;p++)
        load_tile16(p, tid, g_hT + p*16*32, W + (size_t)p*16*VV, VV, v0, sW, sA);

    float4 bv = *(const float4*)(ob + v0 + vl);
    u64 b01 = pk(bv.x,bv.y), b23 = pk(bv.z,bv.w);
    u64 A00=b01,A01=b23,A10=b01,A11=b23,A20=b01,A21=b23,A30=b01,A31=b23;

    for (int u=0; u<64; u++){
        int rem = 63-u;
        if (rem >= 2) CP_WAIT(2);
        else if (rem == 1) CP_WAIT(1);
        else CP_WAIT(0);
        __syncthreads();
        if (u+3 < 64)
            load_tile16((u+3)&3, tid, g_hT + (u+3)*16*32,
                        W + (size_t)(u+3)*16*VV, VV, v0, sW, sA);
        const float* pw = sW[u&3];
        const float* pa = sA[u&3];
        #pragma unroll
        for (int kk=0;kk<16;kk++){
            float4 w = *(const float4*)(pw + kk*128 + vl);
            u64 w01 = pk(w.x,w.y), w23 = pk(w.z,w.w);
            float4 a = *(const float4*)(pa + kk*32 + b0);
            u64 s0=pk(a.x,a.x), s1=pk(a.y,a.y), s2=pk(a.z,a.z), s3=pk(a.w,a.w);
            fma2(A00,s0,w01); fma2(A01,s0,w23);
            fma2(A10,s1,w01); fma2(A11,s1,w23);
            fma2(A20,s2,w01); fma2(A21,s2,w23);
            fma2(A30,s3,w01); fma2(A31,s3,w23);
        }
    }
    float2 r0a=up(A00), r0b=up(A01);
    float2 r1a=up(A10), r1b=up(A11);
    float2 r2a=up(A20), r2b=up(A21);
    float2 r3a=up(A30), r3b=up(A31);
    *(float4*)(out + ((size_t)(b0+0)*LL + t)*VV + v0+vl) = make_float4(r0a.x,r0a.y,r0b.x,r0b.y);
    *(float4*)(out + ((size_t)(b0+1)*LL + t)*VV + v0+vl) = make_float4(r1a.x,r1a.y,r1b.x,r1b.y);
    *(float4*)(out + ((size_t)(b0+2)*LL + t)*VV + v0+vl) = make_float4(r2a.x,r2a.y,r2b.x,r2b.y);
    *(float4*)(out + ((size_t)(b0+3)*LL + t)*VV + v0+vl) = make_float4(r3a.x,r3a.y,r3b.x,r3b.y);
}

// =====================================================================
// log_softmax in-place + argmax (first occurrence)
// =====================================================================
__global__ __launch_bounds__(512) void lsm_argmax(float* __restrict__ out, int t)
{
    int b = blockIdx.x, tid = threadIdx.x;
    float* row = out + ((size_t)b*LL + t)*VV;
    __shared__ float sm[512];
    __shared__ int   si[512];

    float m = -INFINITY; int mi = 0;
    for (int v=tid*4; v<VV; v+=2048){
        float4 xv = *(const float4*)(row+v);
        if (xv.x > m){ m = xv.x; mi = v; }
        if (xv.y > m){ m = xv.y; mi = v+1; }
        if (xv.z > m){ m = xv.z; mi = v+2; }
        if (xv.w > m){ m = xv.w; mi = v+3; }
    }
    sm[tid]=m; si[tid]=mi;
    __syncthreads();
    for (int st=256; st>0; st>>=1){
        if (tid < st){
            float m2=sm[tid+st]; int i2=si[tid+st];
            if (m2 > sm[tid] || (m2==sm[tid] && i2 < si[tid])){
                sm[tid]=m2; si[tid]=i2;
            }
        }
        __syncthreads();
    }
    float gm = sm[0];
    if (tid==0) g_tok[b]=si[0];
    __syncthreads();

    float s = 0.0f;
    for (int v=tid*4; v<VV; v+=2048){
        float4 xv = *(const float4*)(row+v);
        s += expf(xv.x-gm) + expf(xv.y-gm) + expf(xv.z-gm) + expf(xv.w-gm);
    }
    sm[tid]=s;
    __syncthreads();
    for (int st=256; st>0; st>>=1){
        if (tid < st) sm[tid] += sm[tid+st];
        __syncthreads();
    }
    float lse = gm + logf(sm[0]);
    for (int v=tid*4; v<VV; v+=2048){
        float4 xv = *(const float4*)(row+v);
        xv.x -= lse; xv.y -= lse; xv.z -= lse; xv.w -= lse;
        *(float4*)(row+v) = xv;
    }
}

// =====================================================================
extern "C" void kernel_launch(void* const* d_in, const int* in_sizes, int n_in,
                              void* d_out, int out_size)
{
    const int*   x    = (const int*)  d_in[0];
    const float* eemb = (const float*)d_in[1];
    const float* ewx  = (const float*)d_in[2];
    const float* ewh  = (const float*)d_in[3];
    const float* eb   = (const float*)d_in[4];
    const float* demb = (const float*)d_in[5];
    const float* aw   = (const float*)d_in[6];
    const float* ab   = (const float*)d_in[7];
    const float* cw   = (const float*)d_in[8];
    const float* cb   = (const float*)d_in[9];
    const float* dwx  = (const float*)d_in[10];
    const float* dwh  = (const float*)d_in[11];
    const float* db   = (const float*)d_in[12];
    const float* ow   = (const float*)d_in[13];
    const float* obb  = (const float*)d_in[14];
    float* out = (float*)d_out;

    float *p_xembT, *p_hT, *p_inpT, *p_eT, *p_ctxT, *p_part, *p_part2;
    cudaGetSymbolAddress((void**)&p_xembT, g_xembT);
    cudaGetSymbolAddress((void**)&p_hT,    g_hT);
    cudaGetSymbolAddress((void**)&p_inpT,  g_inpT);
    cudaGetSymbolAddress((void**)&p_eT,    g_eT);
    cudaGetSymbolAddress((void**)&p_ctxT,  g_ctxT);
    cudaGetSymbolAddress((void**)&p_part,  g_part);
    cudaGetSymbolAddress((void**)&p_part2, g_part2);

    // ---- encoder ----
    init_state<<<128,256>>>();
    for (int t=0;t<LL;t++){
        gather_embT<<<64,256>>>(x, eemb, t);
        // K = 512 emb (32 units) + 1024 h (64 units) = 96 units; 4 slices x 24
        gemm_seg<<<dim3(32,4),256>>>(p_xembT, ewx, 32, p_hT, ewh, G4, 24, p_part);
        lstm_update<<<128,256>>>(eb, 1, t);
    }

    // ---- decoder ----
    init_state<<<128,256>>>();
    for (int t=0;t<LL;t++){
        attn_ctx<<<BB,256>>>(demb, aw, ab);
        // comb: K = 1024 e + 1024 ctx = 128 units; 16 slices x 8
        gemm_seg<<<dim3(8,16),256>>>(p_eT, cw, 64, p_ctxT, cw + (size_t)1024*HH, HH, 8, p_part2);
        comb_fin<<<128,256>>>(cb);
        // gates: K = 1024 inp + 1024 h = 128 units; 4 slices x 32
        gemm_seg<<<dim3(32,4),256>>>(p_inpT, dwx, 64, p_hT, dwh, G4, 32, p_part);
        lstm_update<<<128,256>>>(db, 0, 0);
        out_proj<<<250,256>>>(ow, obb, out, t);
        lsm_argmax<<<BB,512>>>(out, t);
    }
}